// round 16
// baseline (speedup 1.0000x reference)
#include <cuda_runtime.h>
#include <cuda_fp16.h>

// ---------------------------------------------------------------------------
// Problem constants
// ---------------------------------------------------------------------------
#define Dd 8
#define Hh 24
#define Ww 24
#define NV (Dd * Hh * Ww)     /* 4608 voxels */
#define DIMC 192
#define QPS (2 * NV)          /* queries per scale: 2 heads * 4608 = 9216 */
#define PART_STRIDE 36        /* floats per partial record: 32 acc + l + pad */
#define PART_UNIT (QPS * PART_STRIDE)
#define SCALE_F 0.17677669529663687f  /* 32^-0.5 */

static __device__ __align__(16) __half g_qh[6 * NV * 32];        // 1.7 MB packed Q fp16
static __device__ __align__(16) __half g_kh[6 * NV * 32];        // 1.7 MB packed K fp16 (pre-scaled)
static __device__ __align__(16) __half g_vh[6 * NV * 32];        // 1.7 MB packed V fp16
static __device__ __align__(16) float  g_y[NV * DIMC];           // 3.5 MB
static __device__ __align__(16) float  g_part[15 * PART_UNIT];   // 19.9 MB partials
static __device__ __align__(16) float  g_psum[4 * NV * DIMC];    // 14.2 MB split-K partials

__device__ __forceinline__ int iclamp(int v, int lo, int hi) {
    v = v < lo ? lo : v;
    return v > hi ? hi : v;
}

// ---------------------------------------------------------------------------
// Packed f32x2 helpers (FFMA2 path — 2x FFMA throughput on sm_103a)
// ---------------------------------------------------------------------------
__device__ __forceinline__ unsigned long long pack2(float x, float y) {
    unsigned long long r;
    asm("mov.b64 %0, {%1, %2};" : "=l"(r) : "f"(x), "f"(y));
    return r;
}
__device__ __forceinline__ float2 unpack2(unsigned long long u) {
    float2 r;
    asm("mov.b64 {%0, %1}, %2;" : "=f"(r.x), "=f"(r.y) : "l"(u));
    return r;
}
__device__ __forceinline__ unsigned long long ffma2(
    unsigned long long a, unsigned long long b, unsigned long long c) {
    unsigned long long d;
    asm("fma.rn.f32x2 %0, %1, %2, %3;" : "=l"(d) : "l"(a), "l"(b), "l"(c));
    return d;
}

// ---------------------------------------------------------------------------
// Shared GEMM mainloop body: BM=128, BN=64, BK=16, 256 threads, 8x4 tile,
// double-buffered smem.
// ---------------------------------------------------------------------------
#define GEMM_MAINLOOP(Abase, Bbase, Kd, N, nkt)                                 \
    float4 a0v = *(const float4*)(Abase);                                       \
    float4 a1v = *(const float4*)(Abase + (size_t)64 * (Kd));                   \
    float4 bv  = *(const float4*)(Bbase);                                       \
    As[0][ac * 4 + 0][ar] = a0v.x;  As[0][ac * 4 + 1][ar] = a0v.y;              \
    As[0][ac * 4 + 2][ar] = a0v.z;  As[0][ac * 4 + 3][ar] = a0v.w;              \
    As[0][ac * 4 + 0][ar + 64] = a1v.x;  As[0][ac * 4 + 1][ar + 64] = a1v.y;    \
    As[0][ac * 4 + 2][ar + 64] = a1v.z;  As[0][ac * 4 + 3][ar + 64] = a1v.w;    \
    *(float4*)&Bs[0][br][bc * 4] = bv;                                          \
    __syncthreads();                                                            \
    int buf = 0;                                                                \
    for (int t = 0; t < (nkt); t++) {                                           \
        const bool more = (t + 1 < (nkt));                                      \
        if (more) {                                                             \
            const int kq = (t + 1) * 16;                                        \
            a0v = *(const float4*)(Abase + kq);                                 \
            a1v = *(const float4*)(Abase + (size_t)64 * (Kd) + kq);             \
            bv  = *(const float4*)(Bbase + (size_t)kq * (N));                   \
        }                                                                       \
        _Pragma("unroll")                                                       \
        for (int k = 0; k < 16; k++) {                                          \
            const ulonglong2* Ap = (const ulonglong2*)&As[buf][k][ty * 8];      \
            ulonglong2 a01 = Ap[0];                                             \
            ulonglong2 a23 = Ap[1];                                             \
            float4 b4 = *(const float4*)&Bs[buf][k][tx * 4];                    \
            unsigned long long bb0 = pack2(b4.x, b4.x);                         \
            unsigned long long bb1 = pack2(b4.y, b4.y);                         \
            unsigned long long bb2 = pack2(b4.z, b4.z);                         \
            unsigned long long bb3 = pack2(b4.w, b4.w);                         \
            acc2[0][0] = ffma2(a01.x, bb0, acc2[0][0]);                         \
            acc2[0][1] = ffma2(a01.x, bb1, acc2[0][1]);                         \
            acc2[0][2] = ffma2(a01.x, bb2, acc2[0][2]);                         \
            acc2[0][3] = ffma2(a01.x, bb3, acc2[0][3]);                         \
            acc2[1][0] = ffma2(a01.y, bb0, acc2[1][0]);                         \
            acc2[1][1] = ffma2(a01.y, bb1, acc2[1][1]);                         \
            acc2[1][2] = ffma2(a01.y, bb2, acc2[1][2]);                         \
            acc2[1][3] = ffma2(a01.y, bb3, acc2[1][3]);                         \
            acc2[2][0] = ffma2(a23.x, bb0, acc2[2][0]);                         \
            acc2[2][1] = ffma2(a23.x, bb1, acc2[2][1]);                         \
            acc2[2][2] = ffma2(a23.x, bb2, acc2[2][2]);                         \
            acc2[2][3] = ffma2(a23.x, bb3, acc2[2][3]);                         \
            acc2[3][0] = ffma2(a23.y, bb0, acc2[3][0]);                         \
            acc2[3][1] = ffma2(a23.y, bb1, acc2[3][1]);                         \
            acc2[3][2] = ffma2(a23.y, bb2, acc2[3][2]);                         \
            acc2[3][3] = ffma2(a23.y, bb3, acc2[3][3]);                         \
        }                                                                       \
        if (more) {                                                             \
            const int nb = buf ^ 1;                                             \
            As[nb][ac * 4 + 0][ar] = a0v.x;  As[nb][ac * 4 + 1][ar] = a0v.y;    \
            As[nb][ac * 4 + 2][ar] = a0v.z;  As[nb][ac * 4 + 3][ar] = a0v.w;    \
            As[nb][ac * 4 + 0][ar + 64] = a1v.x;                                \
            As[nb][ac * 4 + 1][ar + 64] = a1v.y;                                \
            As[nb][ac * 4 + 2][ar + 64] = a1v.z;                                \
            As[nb][ac * 4 + 3][ar + 64] = a1v.w;                                \
            *(float4*)&Bs[nb][br][bc * 4] = bv;                                 \
            __syncthreads();                                                    \
            buf = nb;                                                           \
        }                                                                       \
    }

// ---------------------------------------------------------------------------
// GEMM1 (QKV, PACK): packed q/k/v, all fp16 (k pre-scaled by SCALE_F).
// ---------------------------------------------------------------------------
__global__ __launch_bounds__(256) void gemm_qkv_kernel(
    const float* __restrict__ A, const float* __restrict__ B,
    const float* __restrict__ bias,
    __half* __restrict__ gqh, __half* __restrict__ gkh, __half* __restrict__ gvh,
    int M, int N, int Kd)
{
    __shared__ __align__(16) float As[2][16][132];
    __shared__ __align__(16) float Bs[2][16][64];

    const int tid = threadIdx.x;
    const int tx = tid & 15;
    const int ty = tid >> 4;
    const int row0 = blockIdx.y * 128;
    const int col0 = blockIdx.x * 64;

    const int ar = tid >> 2;
    const int ac = tid & 3;
    const int br = tid >> 4;
    const int bc = tid & 15;

    const float* Abase = A + (size_t)(row0 + ar) * Kd + ac * 4;
    const float* Bbase = B + (size_t)br * N + col0 + bc * 4;

    unsigned long long acc2[4][4];
#pragma unroll
    for (int mp = 0; mp < 4; mp++)
#pragma unroll
        for (int n = 0; n < 4; n++) acc2[mp][n] = 0ull;

    GEMM_MAINLOOP(Abase, Bbase, Kd, N, Kd / 16)

    float4 bias4 = *(const float4*)(bias + col0 + tx * 4);

    const int region = col0 >> 6;        // 0..8
    const int kind   = region % 3;       // 0=q 1=k 2=v
    const int scale  = region / 3;
    const int head   = tx >> 3;
    const int ch     = (tx * 4) & 31;
    const int hg     = scale * 2 + head;

    const float sc = (kind == 1) ? SCALE_F : 1.0f;
    __half* base = (kind == 0) ? gqh : (kind == 1) ? gkh : gvh;

#pragma unroll
    for (int mp = 0; mp < 4; mp++) {
        float2 f0 = unpack2(acc2[mp][0]);
        float2 f1 = unpack2(acc2[mp][1]);
        float2 f2 = unpack2(acc2[mp][2]);
        float2 f3 = unpack2(acc2[mp][3]);
        float4 lo = make_float4(f0.x + bias4.x, f1.x + bias4.y,
                                f2.x + bias4.z, f3.x + bias4.w);
        float4 hi = make_float4(f0.y + bias4.x, f1.y + bias4.y,
                                f2.y + bias4.z, f3.y + bias4.w);
        const int r_lo = row0 + ty * 8 + 2 * mp;
        __half2 l01 = __floats2half2_rn(lo.x * sc, lo.y * sc);
        __half2 l23 = __floats2half2_rn(lo.z * sc, lo.w * sc);
        __half2 h01 = __floats2half2_rn(hi.x * sc, hi.y * sc);
        __half2 h23 = __floats2half2_rn(hi.z * sc, hi.w * sc);
        uint2 ul = make_uint2(*(unsigned*)&l01, *(unsigned*)&l23);
        uint2 uh = make_uint2(*(unsigned*)&h01, *(unsigned*)&h23);
        *(uint2*)(base + ((size_t)hg * NV + r_lo) * 32 + ch) = ul;
        *(uint2*)(base + ((size_t)hg * NV + r_lo + 1) * 32 + ch) = uh;
    }
}

// ---------------------------------------------------------------------------
// GEMM2 (proj), split-K=4. BM=128, BN=64. Grid (3, 36, 4) = 432 blocks.
// ---------------------------------------------------------------------------
__global__ __launch_bounds__(256) void gemm_splitk_kernel(
    const float* __restrict__ A, const float* __restrict__ B,
    float* __restrict__ psum, int M, int N, int Kd, int nkt)
{
    __shared__ __align__(16) float As[2][16][132];
    __shared__ __align__(16) float Bs[2][16][64];

    const int tid = threadIdx.x;
    const int tx = tid & 15;
    const int ty = tid >> 4;
    const int row0 = blockIdx.y * 128;
    const int col0 = blockIdx.x * 64;
    const int k0   = blockIdx.z * nkt * 16;

    const int ar = tid >> 2;
    const int ac = tid & 3;
    const int br = tid >> 4;
    const int bc = tid & 15;

    const float* Abase = A + (size_t)(row0 + ar) * Kd + k0 + ac * 4;
    const float* Bbase = B + (size_t)(k0 + br) * N + col0 + bc * 4;

    unsigned long long acc2[4][4];
#pragma unroll
    for (int mp = 0; mp < 4; mp++)
#pragma unroll
        for (int n = 0; n < 4; n++) acc2[mp][n] = 0ull;

    GEMM_MAINLOOP(Abase, Bbase, Kd, N, nkt)

    float* out = psum + (size_t)blockIdx.z * M * N;
#pragma unroll
    for (int mp = 0; mp < 4; mp++) {
        float2 f0 = unpack2(acc2[mp][0]);
        float2 f1 = unpack2(acc2[mp][1]);
        float2 f2 = unpack2(acc2[mp][2]);
        float2 f3 = unpack2(acc2[mp][3]);
        const int r_lo = row0 + ty * 8 + 2 * mp;
        *(float4*)(out + (size_t)r_lo * N + col0 + tx * 4) =
            make_float4(f0.x, f1.x, f2.x, f3.x);
        *(float4*)(out + (size_t)(r_lo + 1) * N + col0 + tx * 4) =
            make_float4(f0.y, f1.y, f2.y, f3.y);
    }
}

// Split-K reduction: out = p0+p1+p2+p3 + bias.
__global__ __launch_bounds__(256) void splitk_reduce4_kernel(
    const float* __restrict__ psum, const float* __restrict__ bias,
    float* __restrict__ out)
{
    const int i = (blockIdx.x * 256 + threadIdx.x) * 4;
    const size_t stride = (size_t)NV * DIMC;
    float4 a = *(const float4*)(psum + i);
    float4 b = *(const float4*)(psum + stride + i);
    float4 c = *(const float4*)(psum + 2 * stride + i);
    float4 d = *(const float4*)(psum + 3 * stride + i);
    float4 bi = *(const float4*)(bias + (i % DIMC));
    *(float4*)(out + i) = make_float4(a.x + b.x + c.x + d.x + bi.x,
                                      a.y + b.y + c.y + d.y + bi.y,
                                      a.z + b.z + c.z + d.z + bi.z,
                                      a.w + b.w + c.w + d.w + bi.w);
}

// ---------------------------------------------------------------------------
// NA3D partial attention, 2-LANE query split (lane t in {0,1} owns 16 ch of
// one query), ONE depth slice per chunk. Per warp-iteration 16 queries are
// served by ~26 instructions (1.6 warp-instr per query-neighbor) and the
// logit reduction needs only ONE shfl. HFMA2 math; per-row half2 accum
// flushed to fp32. No-max softmax (logits tiny).
// ---------------------------------------------------------------------------
template <int K>
__device__ __forceinline__ void na_body(
    const __half* __restrict__ gqh,
    const __half* __restrict__ kh, const __half* __restrict__ vh,
    float* __restrict__ part, int hgbase, int bidx, int c)
{
    const int g = bidx * 256 + threadIdx.x;
    const int t = g & 1;
    int r = g >> 1;
    const int w = r % 24; r /= 24;
    const int h = r % 24; r /= 24;
    const int d = r & 7;
    const int head = r >> 3;

    const int start_d = iclamp(d - K / 2, 0, Dd - K);
    const int start_h = iclamp(h - K / 2, 0, Hh - K);
    const int start_w = iclamp(w - K / 2, 0, Ww - K);
    const int dd = start_d + c;

    const int hg = hgbase + head;
    const int qrow = (d * Hh + h) * Ww + w;

    // q: 16 fp16 channels = 2 uint4
    const __half* qp = gqh + ((size_t)hg * NV + qrow) * 32 + t * 16;
    const uint4 qa = *(const uint4*)qp;
    const uint4 qb = *(const uint4*)(qp + 8);
    __half2 qh[8];
    qh[0] = *(const __half2*)&qa.x;  qh[1] = *(const __half2*)&qa.y;
    qh[2] = *(const __half2*)&qa.z;  qh[3] = *(const __half2*)&qa.w;
    qh[4] = *(const __half2*)&qb.x;  qh[5] = *(const __half2*)&qb.y;
    qh[6] = *(const __half2*)&qb.z;  qh[7] = *(const __half2*)&qb.w;

    const __half* kbase = kh + (size_t)hg * NV * 32 + t * 16;
    const __half* vbase = vh + (size_t)hg * NV * 32 + t * 16;

    float l = 0.f;
    float fa[16];
#pragma unroll
    for (int i = 0; i < 16; i++) fa[i] = 0.f;

    for (int hh = 0; hh < K; hh++) {
        const int rowbase = (dd * Hh + start_h + hh) * Ww + start_w;
        __half2 a2[8];
#pragma unroll
        for (int x = 0; x < 8; x++) a2[x] = __floats2half2_rn(0.f, 0.f);
#pragma unroll
        for (int ww = 0; ww < K; ww++) {
            const int row = rowbase + ww;
            const uint4 ka = *(const uint4*)(kbase + (size_t)row * 32);
            const uint4 kb = *(const uint4*)(kbase + (size_t)row * 32 + 8);
            __half2 s2 = __hmul2(qh[0], *(const __half2*)&ka.x);
            s2 = __hfma2(qh[1], *(const __half2*)&ka.y, s2);
            s2 = __hfma2(qh[2], *(const __half2*)&ka.z, s2);
            s2 = __hfma2(qh[3], *(const __half2*)&ka.w, s2);
            s2 = __hfma2(qh[4], *(const __half2*)&kb.x, s2);
            s2 = __hfma2(qh[5], *(const __half2*)&kb.y, s2);
            s2 = __hfma2(qh[6], *(const __half2*)&kb.z, s2);
            s2 = __hfma2(qh[7], *(const __half2*)&kb.w, s2);
            float2 sf = __half22float2(s2);
            float s = sf.x + sf.y;
            s += __shfl_xor_sync(0xffffffffu, s, 1);

            float p = __expf(s);
            l += p;
            __half2 pp = __half2half2(__float2half_rn(p));
            const uint4 va = *(const uint4*)(vbase + (size_t)row * 32);
            const uint4 vb = *(const uint4*)(vbase + (size_t)row * 32 + 8);
            a2[0] = __hfma2(pp, *(const __half2*)&va.x, a2[0]);
            a2[1] = __hfma2(pp, *(const __half2*)&va.y, a2[1]);
            a2[2] = __hfma2(pp, *(const __half2*)&va.z, a2[2]);
            a2[3] = __hfma2(pp, *(const __half2*)&va.w, a2[3]);
            a2[4] = __hfma2(pp, *(const __half2*)&vb.x, a2[4]);
            a2[5] = __hfma2(pp, *(const __half2*)&vb.y, a2[5]);
            a2[6] = __hfma2(pp, *(const __half2*)&vb.z, a2[6]);
            a2[7] = __hfma2(pp, *(const __half2*)&vb.w, a2[7]);
        }
#pragma unroll
        for (int x = 0; x < 8; x++) {
            float2 fj = __half22float2(a2[x]);
            fa[2 * x]     += fj.x;
            fa[2 * x + 1] += fj.y;
        }
    }

    const int qidx = ((head * Dd + d) * Hh + h) * Ww + w;
    float* pb = part + (size_t)qidx * PART_STRIDE + t * 16;
#pragma unroll
    for (int j = 0; j < 4; j++)
        *(float4*)(pb + j * 4) = make_float4(fa[4 * j], fa[4 * j + 1],
                                             fa[4 * j + 2], fa[4 * j + 3]);
    if (t == 0) part[(size_t)qidx * PART_STRIDE + 32] = l;
}

// One launch, all scales, 1 slice/chunk, 72 blocks per chunk (2-lane).
// Part units: K3 -> 0..2, K5 -> 3..7, K7 -> 8..14. K7 (heaviest) first.
// Block ranges: K7 [0,504), K5 [504,864), K3 [864,1080).
__global__ __launch_bounds__(256) void na_partial_all_kernel(
    const __half* __restrict__ gqh,
    const __half* __restrict__ kh, const __half* __restrict__ vh,
    float* __restrict__ part)
{
    const int b = blockIdx.x;
    if (b < 504) {
        const int c = b / 72;
        na_body<7>(gqh, kh, vh, part + (size_t)(8 + c) * PART_UNIT, 4, b - c * 72, c);
    } else if (b < 864) {
        const int bb = b - 504;
        const int c = bb / 72;
        na_body<5>(gqh, kh, vh, part + (size_t)(3 + c) * PART_UNIT, 2, bb - c * 72, c);
    } else {
        const int bb = b - 864;
        const int c = bb / 72;
        na_body<3>(gqh, kh, vh, part + (size_t)c * PART_UNIT, 0, bb - c * 72, c);
    }
}

// ---------------------------------------------------------------------------
// Combine partials (plain sums) across chunks -> g_y. 110592 threads.
// scale s: cnt = 2s+3 chunks, unit base = s*(s+2).
// ---------------------------------------------------------------------------
__global__ __launch_bounds__(256) void na_combine_kernel(
    const float* __restrict__ part, float* __restrict__ y)
{
    const int g = blockIdx.x * 256 + threadIdx.x;
    const int t = g & 3;
    int r = g >> 2;
    const int w = r % 24; r /= 24;
    const int h = r % 24; r /= 24;
    const int d = r & 7;  r >>= 3;
    const int head = r & 1;
    const int s = r >> 1;

    const int cnt = 2 * s + 3;
    const size_t base = (size_t)PART_UNIT * (size_t)(s * (s + 2));
    const int qidx = ((head * Dd + d) * Hh + h) * Ww + w;

    float L = 0.f;
    float o[8];
#pragma unroll
    for (int i = 0; i < 8; i++) o[i] = 0.f;
    for (int c = 0; c < cnt; c++) {
        const float* pb = part + base + (size_t)c * PART_UNIT
                        + (size_t)qidx * PART_STRIDE;
        L += pb[32];
        float4 a0 = *(const float4*)(pb + t * 8);
        float4 a1 = *(const float4*)(pb + t * 8 + 4);
        o[0] += a0.x; o[1] += a0.y; o[2] += a0.z; o[3] += a0.w;
        o[4] += a1.x; o[5] += a1.y; o[6] += a1.z; o[7] += a1.w;
    }
    float inv = 1.f / L;
    const int vr = (d * Hh + h) * Ww + w;
    float* yp = y + (size_t)vr * DIMC + s * 64 + head * 32 + t * 8;
    *(float4*)yp       = make_float4(o[0] * inv, o[1] * inv, o[2] * inv, o[3] * inv);
    *(float4*)(yp + 4) = make_float4(o[4] * inv, o[5] * inv, o[6] * inv, o[7] * inv);
}

// ---------------------------------------------------------------------------
// Launch
// ---------------------------------------------------------------------------
extern "C" void kernel_launch(void* const* d_in, const int* in_sizes, int n_in,
                              void* d_out, int out_size)
{
    (void)in_sizes; (void)n_in; (void)out_size;
    const float* x      = (const float*)d_in[0];
    const float* W_qkv  = (const float*)d_in[1];
    const float* b_qkv  = (const float*)d_in[2];
    const float* W_proj = (const float*)d_in[3];
    const float* b_proj = (const float*)d_in[4];
    float* out = (float*)d_out;

    __half* qh;   cudaGetSymbolAddress((void**)&qh,   g_qh);
    __half* kh;   cudaGetSymbolAddress((void**)&kh,   g_kh);
    __half* vh;   cudaGetSymbolAddress((void**)&vh,   g_vh);
    float*  y;    cudaGetSymbolAddress((void**)&y,    g_y);
    float*  part; cudaGetSymbolAddress((void**)&part, g_part);
    float*  psum; cudaGetSymbolAddress((void**)&psum, g_psum);

    // 1) fused QKV GEMM + fp16 pack (324 blocks, double-buffered)
    gemm_qkv_kernel<<<dim3(576 / 64, NV / 128), 256>>>(
        x, W_qkv, b_qkv, qh, kh, vh, NV, 576, DIMC);

    // 2) all-scale NA3D partials, 2-lane, 1 slice/chunk (1080 blocks)
    na_partial_all_kernel<<<1080, 256>>>(qh, kh, vh, part);

    // 3) combine partials -> y
    na_combine_kernel<<<110592 / 256, 256>>>(part, y);

    // 4) proj GEMM, split-K=4 in ONE launch (3 x 36 x 4 = 432 blocks, BM=128)
    gemm_splitk_kernel<<<dim3(DIMC / 64, NV / 128, 4), 256>>>(
        y, W_proj, psum, NV, DIMC, DIMC, 3);

    // 5) out = sum(psum[0..3]) + bias
    splitk_reduce4_kernel<<<(NV * DIMC / 4) / 256, 256>>>(psum, b_proj, out);
}

// round 17
// speedup vs baseline: 1.2103x; 1.2103x over previous
#include <cuda_runtime.h>
#include <cuda_fp16.h>

// ---------------------------------------------------------------------------
// Problem constants
// ---------------------------------------------------------------------------
#define Dd 8
#define Hh 24
#define Ww 24
#define NV (Dd * Hh * Ww)     /* 4608 voxels */
#define DIMC 192
#define QPS (2 * NV)          /* queries per scale: 2 heads * 4608 = 9216 */
#define PART_STRIDE 36        /* floats per partial record: 32 acc + l + pad */
#define PART_UNIT (QPS * PART_STRIDE)
#define SCALE_F 0.17677669529663687f  /* 32^-0.5 */
/* k pre-scale includes log2(e): softmax(s) == softmax_base2(s*log2e) */
#define KSCALE (0.17677669529663687f * 1.4426950408889634f)

static __device__ __align__(16) __half g_qh[6 * NV * 32];        // 1.7 MB packed Q fp16
static __device__ __align__(16) __half g_kh[6 * NV * 32];        // 1.7 MB packed K fp16 (pre-scaled)
static __device__ __align__(16) __half g_vh[6 * NV * 32];        // 1.7 MB packed V fp16
static __device__ __align__(16) float  g_y[NV * DIMC];           // 3.5 MB
static __device__ __align__(16) float  g_part[17 * PART_UNIT];   // 22.6 MB partials
static __device__ __align__(16) float  g_psum[4 * NV * DIMC];    // 14.2 MB split-K partials

__device__ __forceinline__ int iclamp(int v, int lo, int hi) {
    v = v < lo ? lo : v;
    return v > hi ? hi : v;
}

// ---------------------------------------------------------------------------
// Packed f32x2 helpers (FFMA2 path — 2x FFMA throughput on sm_103a)
// ---------------------------------------------------------------------------
__device__ __forceinline__ unsigned long long pack2(float x, float y) {
    unsigned long long r;
    asm("mov.b64 %0, {%1, %2};" : "=l"(r) : "f"(x), "f"(y));
    return r;
}
__device__ __forceinline__ float2 unpack2(unsigned long long u) {
    float2 r;
    asm("mov.b64 {%0, %1}, %2;" : "=f"(r.x), "=f"(r.y) : "l"(u));
    return r;
}
__device__ __forceinline__ unsigned long long ffma2(
    unsigned long long a, unsigned long long b, unsigned long long c) {
    unsigned long long d;
    asm("fma.rn.f32x2 %0, %1, %2, %3;" : "=l"(d) : "l"(a), "l"(b), "l"(c));
    return d;
}

// ---------------------------------------------------------------------------
// Shared GEMM mainloop body: BM=128, BN=64, BK=16, 256 threads, 8x4 tile,
// double-buffered smem.
// ---------------------------------------------------------------------------
#define GEMM_MAINLOOP(Abase, Bbase, Kd, N, nkt)                                 \
    float4 a0v = *(const float4*)(Abase);                                       \
    float4 a1v = *(const float4*)(Abase + (size_t)64 * (Kd));                   \
    float4 bv  = *(const float4*)(Bbase);                                       \
    As[0][ac * 4 + 0][ar] = a0v.x;  As[0][ac * 4 + 1][ar] = a0v.y;              \
    As[0][ac * 4 + 2][ar] = a0v.z;  As[0][ac * 4 + 3][ar] = a0v.w;              \
    As[0][ac * 4 + 0][ar + 64] = a1v.x;  As[0][ac * 4 + 1][ar + 64] = a1v.y;    \
    As[0][ac * 4 + 2][ar + 64] = a1v.z;  As[0][ac * 4 + 3][ar + 64] = a1v.w;    \
    *(float4*)&Bs[0][br][bc * 4] = bv;                                          \
    __syncthreads();                                                            \
    int buf = 0;                                                                \
    for (int t = 0; t < (nkt); t++) {                                           \
        const bool more = (t + 1 < (nkt));                                      \
        if (more) {                                                             \
            const int kq = (t + 1) * 16;                                        \
            a0v = *(const float4*)(Abase + kq);                                 \
            a1v = *(const float4*)(Abase + (size_t)64 * (Kd) + kq);             \
            bv  = *(const float4*)(Bbase + (size_t)kq * (N));                   \
        }                                                                       \
        _Pragma("unroll")                                                       \
        for (int k = 0; k < 16; k++) {                                          \
            const ulonglong2* Ap = (const ulonglong2*)&As[buf][k][ty * 8];      \
            ulonglong2 a01 = Ap[0];                                             \
            ulonglong2 a23 = Ap[1];                                             \
            float4 b4 = *(const float4*)&Bs[buf][k][tx * 4];                    \
            unsigned long long bb0 = pack2(b4.x, b4.x);                         \
            unsigned long long bb1 = pack2(b4.y, b4.y);                         \
            unsigned long long bb2 = pack2(b4.z, b4.z);                         \
            unsigned long long bb3 = pack2(b4.w, b4.w);                         \
            acc2[0][0] = ffma2(a01.x, bb0, acc2[0][0]);                         \
            acc2[0][1] = ffma2(a01.x, bb1, acc2[0][1]);                         \
            acc2[0][2] = ffma2(a01.x, bb2, acc2[0][2]);                         \
            acc2[0][3] = ffma2(a01.x, bb3, acc2[0][3]);                         \
            acc2[1][0] = ffma2(a01.y, bb0, acc2[1][0]);                         \
            acc2[1][1] = ffma2(a01.y, bb1, acc2[1][1]);                         \
            acc2[1][2] = ffma2(a01.y, bb2, acc2[1][2]);                         \
            acc2[1][3] = ffma2(a01.y, bb3, acc2[1][3]);                         \
            acc2[2][0] = ffma2(a23.x, bb0, acc2[2][0]);                         \
            acc2[2][1] = ffma2(a23.x, bb1, acc2[2][1]);                         \
            acc2[2][2] = ffma2(a23.x, bb2, acc2[2][2]);                         \
            acc2[2][3] = ffma2(a23.x, bb3, acc2[2][3]);                         \
            acc2[3][0] = ffma2(a23.y, bb0, acc2[3][0]);                         \
            acc2[3][1] = ffma2(a23.y, bb1, acc2[3][1]);                         \
            acc2[3][2] = ffma2(a23.y, bb2, acc2[3][2]);                         \
            acc2[3][3] = ffma2(a23.y, bb3, acc2[3][3]);                         \
        }                                                                       \
        if (more) {                                                             \
            const int nb = buf ^ 1;                                             \
            As[nb][ac * 4 + 0][ar] = a0v.x;  As[nb][ac * 4 + 1][ar] = a0v.y;    \
            As[nb][ac * 4 + 2][ar] = a0v.z;  As[nb][ac * 4 + 3][ar] = a0v.w;    \
            As[nb][ac * 4 + 0][ar + 64] = a1v.x;                                \
            As[nb][ac * 4 + 1][ar + 64] = a1v.y;                                \
            As[nb][ac * 4 + 2][ar + 64] = a1v.z;                                \
            As[nb][ac * 4 + 3][ar + 64] = a1v.w;                                \
            *(float4*)&Bs[nb][br][bc * 4] = bv;                                 \
            __syncthreads();                                                    \
            buf = nb;                                                           \
        }                                                                       \
    }

// ---------------------------------------------------------------------------
// GEMM1 (QKV, PACK): packed q/k/v, all fp16 (k pre-scaled by KSCALE).
// ---------------------------------------------------------------------------
__global__ __launch_bounds__(256) void gemm_qkv_kernel(
    const float* __restrict__ A, const float* __restrict__ B,
    const float* __restrict__ bias,
    __half* __restrict__ gqh, __half* __restrict__ gkh, __half* __restrict__ gvh,
    int M, int N, int Kd)
{
    __shared__ __align__(16) float As[2][16][132];
    __shared__ __align__(16) float Bs[2][16][64];

    const int tid = threadIdx.x;
    const int tx = tid & 15;
    const int ty = tid >> 4;
    const int row0 = blockIdx.y * 128;
    const int col0 = blockIdx.x * 64;

    const int ar = tid >> 2;
    const int ac = tid & 3;
    const int br = tid >> 4;
    const int bc = tid & 15;

    const float* Abase = A + (size_t)(row0 + ar) * Kd + ac * 4;
    const float* Bbase = B + (size_t)br * N + col0 + bc * 4;

    unsigned long long acc2[4][4];
#pragma unroll
    for (int mp = 0; mp < 4; mp++)
#pragma unroll
        for (int n = 0; n < 4; n++) acc2[mp][n] = 0ull;

    GEMM_MAINLOOP(Abase, Bbase, Kd, N, Kd / 16)

    float4 bias4 = *(const float4*)(bias + col0 + tx * 4);

    const int region = col0 >> 6;        // 0..8
    const int kind   = region % 3;       // 0=q 1=k 2=v
    const int scale  = region / 3;
    const int head   = tx >> 3;
    const int ch     = (tx * 4) & 31;
    const int hg     = scale * 2 + head;

    const float sc = (kind == 1) ? KSCALE : 1.0f;
    __half* base = (kind == 0) ? gqh : (kind == 1) ? gkh : gvh;

#pragma unroll
    for (int mp = 0; mp < 4; mp++) {
        float2 f0 = unpack2(acc2[mp][0]);
        float2 f1 = unpack2(acc2[mp][1]);
        float2 f2 = unpack2(acc2[mp][2]);
        float2 f3 = unpack2(acc2[mp][3]);
        float4 lo = make_float4(f0.x + bias4.x, f1.x + bias4.y,
                                f2.x + bias4.z, f3.x + bias4.w);
        float4 hi = make_float4(f0.y + bias4.x, f1.y + bias4.y,
                                f2.y + bias4.z, f3.y + bias4.w);
        const int r_lo = row0 + ty * 8 + 2 * mp;
        __half2 l01 = __floats2half2_rn(lo.x * sc, lo.y * sc);
        __half2 l23 = __floats2half2_rn(lo.z * sc, lo.w * sc);
        __half2 h01 = __floats2half2_rn(hi.x * sc, hi.y * sc);
        __half2 h23 = __floats2half2_rn(hi.z * sc, hi.w * sc);
        uint2 ul = make_uint2(*(unsigned*)&l01, *(unsigned*)&l23);
        uint2 uh = make_uint2(*(unsigned*)&h01, *(unsigned*)&h23);
        *(uint2*)(base + ((size_t)hg * NV + r_lo) * 32 + ch) = ul;
        *(uint2*)(base + ((size_t)hg * NV + r_lo + 1) * 32 + ch) = uh;
    }
}

// ---------------------------------------------------------------------------
// GEMM2 (proj), split-K=4. BM=128, BN=64. Grid (3, 36, 4) = 432 blocks.
// ---------------------------------------------------------------------------
__global__ __launch_bounds__(256) void gemm_splitk_kernel(
    const float* __restrict__ A, const float* __restrict__ B,
    float* __restrict__ psum, int M, int N, int Kd, int nkt)
{
    __shared__ __align__(16) float As[2][16][132];
    __shared__ __align__(16) float Bs[2][16][64];

    const int tid = threadIdx.x;
    const int tx = tid & 15;
    const int ty = tid >> 4;
    const int row0 = blockIdx.y * 128;
    const int col0 = blockIdx.x * 64;
    const int k0   = blockIdx.z * nkt * 16;

    const int ar = tid >> 2;
    const int ac = tid & 3;
    const int br = tid >> 4;
    const int bc = tid & 15;

    const float* Abase = A + (size_t)(row0 + ar) * Kd + k0 + ac * 4;
    const float* Bbase = B + (size_t)(k0 + br) * N + col0 + bc * 4;

    unsigned long long acc2[4][4];
#pragma unroll
    for (int mp = 0; mp < 4; mp++)
#pragma unroll
        for (int n = 0; n < 4; n++) acc2[mp][n] = 0ull;

    GEMM_MAINLOOP(Abase, Bbase, Kd, N, nkt)

    float* out = psum + (size_t)blockIdx.z * M * N;
#pragma unroll
    for (int mp = 0; mp < 4; mp++) {
        float2 f0 = unpack2(acc2[mp][0]);
        float2 f1 = unpack2(acc2[mp][1]);
        float2 f2 = unpack2(acc2[mp][2]);
        float2 f3 = unpack2(acc2[mp][3]);
        const int r_lo = row0 + ty * 8 + 2 * mp;
        *(float4*)(out + (size_t)r_lo * N + col0 + tx * 4) =
            make_float4(f0.x, f1.x, f2.x, f3.x);
        *(float4*)(out + (size_t)(r_lo + 1) * N + col0 + tx * 4) =
            make_float4(f0.y, f1.y, f2.y, f3.y);
    }
}

// Split-K reduction: out = p0+p1+p2+p3 + bias.
__global__ __launch_bounds__(256) void splitk_reduce4_kernel(
    const float* __restrict__ psum, const float* __restrict__ bias,
    float* __restrict__ out)
{
    const int i = (blockIdx.x * 256 + threadIdx.x) * 4;
    const size_t stride = (size_t)NV * DIMC;
    float4 a = *(const float4*)(psum + i);
    float4 b = *(const float4*)(psum + stride + i);
    float4 c = *(const float4*)(psum + 2 * stride + i);
    float4 d = *(const float4*)(psum + 3 * stride + i);
    float4 bi = *(const float4*)(bias + (i % DIMC));
    *(float4*)(out + i) = make_float4(a.x + b.x + c.x + d.x + bi.x,
                                      a.y + b.y + c.y + d.y + bi.y,
                                      a.z + b.z + c.z + d.z + bi.z,
                                      a.w + b.w + c.w + d.w + bi.w);
}

// ---------------------------------------------------------------------------
// NA3D partial attention, d-PAIRED (R14 structure, packed fp16 logit path):
// thread owns queries (d0=2*dp, d0+1); each k/v row load serves both.
// Logit pair packed into one half2 -> 2 shfl + 3 HADD2 reduction, one HADD2
// mask (0 / -30000 -> exp2 gives exact 0), ONE h2exp2 for both p's.
// k is pre-scaled by SCALE*log2e so exp2 == exp(SCALE * q.k).
// Warp = 8 consecutive w x 4 lanes -> 512B contiguous k/v loads.
// ---------------------------------------------------------------------------
template <int K>
__device__ __forceinline__ void na_body(
    const __half* __restrict__ gqh,
    const __half* __restrict__ kh, const __half* __restrict__ vh,
    float* __restrict__ part, int hgbase, int bidx, int j)
{
    const int g = bidx * 256 + threadIdx.x;
    const int t = g & 3;
    int r = g >> 2;
    const int w = r % 24; r /= 24;
    const int h = r % 24; r /= 24;
    const int dp = r & 3;
    const int head = r >> 2;
    const int d0 = 2 * dp;

    const int s0d = iclamp(d0 - K / 2, 0, Dd - K);
    const int s1d = iclamp(d0 + 1 - K / 2, 0, Dd - K);
    const int ds = s1d - s0d;                       // 0 or 1 (warp-uniform)
    const int start_h = iclamp(h - K / 2, 0, Hh - K);
    const int start_w = iclamp(w - K / 2, 0, Ww - K);

    const int hg = hgbase + head;
    const int qidx0 = ((head * Dd + d0) * Hh + h) * Ww + w;
    float* pb0 = part + (size_t)qidx0 * PART_STRIDE;
    float* pb1 = pb0 + (size_t)(Hh * Ww) * PART_STRIDE;

    if (j >= K + ds) {   // outside union window (warp-uniform): zero records
        float4 z = make_float4(0.f, 0.f, 0.f, 0.f);
        *(float4*)(pb0 + t * 8) = z;  *(float4*)(pb0 + t * 8 + 4) = z;
        *(float4*)(pb1 + t * 8) = z;  *(float4*)(pb1 + t * 8 + 4) = z;
        if (t == 0) { pb0[32] = 0.f; pb1[32] = 0.f; }
        return;
    }
    const bool use0 = (j < K);       // q0 window = [s0d, s0d+K)
    const bool use1 = (j >= ds);     // q1 window = [s0d+ds, s0d+ds+K)
    const int dd = s0d + j;

    // per-chunk mask: 0 keeps logit, -30000 forces exp2 -> exact 0
    const __half2 maskh2 = __floats2half2_rn(use0 ? 0.f : -30000.f,
                                             use1 ? 0.f : -30000.f);

    // load both q vectors (8 fp16 = one uint4 each)
    const int qrow0 = (d0 * Hh + h) * Ww + w;
    const __half* qp0 = gqh + ((size_t)hg * NV + qrow0) * 32 + t * 8;
    const uint4 qa = *(const uint4*)qp0;
    const uint4 qb = *(const uint4*)(qp0 + (size_t)(Hh * Ww) * 32);
    __half2 qh0[4], qh1[4];
    qh0[0] = *(const __half2*)&qa.x;  qh0[1] = *(const __half2*)&qa.y;
    qh0[2] = *(const __half2*)&qa.z;  qh0[3] = *(const __half2*)&qa.w;
    qh1[0] = *(const __half2*)&qb.x;  qh1[1] = *(const __half2*)&qb.y;
    qh1[2] = *(const __half2*)&qb.z;  qh1[3] = *(const __half2*)&qb.w;

    const __half* kbase = kh + (size_t)hg * NV * 32 + t * 8;
    const __half* vbase = vh + (size_t)hg * NV * 32 + t * 8;

    float l0 = 0.f, l1 = 0.f;
    float fa0[8], fa1[8];
#pragma unroll
    for (int i = 0; i < 8; i++) { fa0[i] = 0.f; fa1[i] = 0.f; }

    for (int hh = 0; hh < K; hh++) {
        const int rowbase = (dd * Hh + start_h + hh) * Ww + start_w;
        __half2 a20[4], a21[4];
#pragma unroll
        for (int x = 0; x < 4; x++) {
            a20[x] = __floats2half2_rn(0.f, 0.f);
            a21[x] = __floats2half2_rn(0.f, 0.f);
        }
#pragma unroll
        for (int ww = 0; ww < K; ww++) {
            const int row = rowbase + ww;
            const uint4 k4 = *(const uint4*)(kbase + (size_t)row * 32);
            __half2 s20 = __hmul2(qh0[0], *(const __half2*)&k4.x);
            __half2 s21 = __hmul2(qh1[0], *(const __half2*)&k4.x);
            s20 = __hfma2(qh0[1], *(const __half2*)&k4.y, s20);
            s21 = __hfma2(qh1[1], *(const __half2*)&k4.y, s21);
            s20 = __hfma2(qh0[2], *(const __half2*)&k4.z, s20);
            s21 = __hfma2(qh1[2], *(const __half2*)&k4.z, s21);
            s20 = __hfma2(qh0[3], *(const __half2*)&k4.w, s20);
            s21 = __hfma2(qh1[3], *(const __half2*)&k4.w, s21);
            // pack per-lane pair partial: (sum s20, sum s21)
            __half2 s01 = __hadd2(__lows2half2(s20, s21),
                                  __highs2half2(s20, s21));
            // reduce over 4-lane group (packed, 2 shfl + 2 hadd2)
            unsigned su = *(unsigned*)&s01;
            unsigned sx = __shfl_xor_sync(0xffffffffu, su, 1);
            s01 = __hadd2(s01, *(__half2*)&sx);
            su = *(unsigned*)&s01;
            sx = __shfl_xor_sync(0xffffffffu, su, 2);
            s01 = __hadd2(s01, *(__half2*)&sx);
            // mask + packed exp2 (one MUFU for both queries)
            s01 = __hadd2(s01, maskh2);
            __half2 p2 = h2exp2(s01);
            float2 pf = __half22float2(p2);
            l0 += pf.x;
            l1 += pf.y;
            __half2 pp0 = __half2half2(__low2half(p2));
            __half2 pp1 = __half2half2(__high2half(p2));
            const uint4 v4 = *(const uint4*)(vbase + (size_t)row * 32);
            a20[0] = __hfma2(pp0, *(const __half2*)&v4.x, a20[0]);
            a21[0] = __hfma2(pp1, *(const __half2*)&v4.x, a21[0]);
            a20[1] = __hfma2(pp0, *(const __half2*)&v4.y, a20[1]);
            a21[1] = __hfma2(pp1, *(const __half2*)&v4.y, a21[1]);
            a20[2] = __hfma2(pp0, *(const __half2*)&v4.z, a20[2]);
            a21[2] = __hfma2(pp1, *(const __half2*)&v4.z, a21[2]);
            a20[3] = __hfma2(pp0, *(const __half2*)&v4.w, a20[3]);
            a21[3] = __hfma2(pp1, *(const __half2*)&v4.w, a21[3]);
        }
#pragma unroll
        for (int x = 0; x < 4; x++) {
            float2 f0 = __half22float2(a20[x]);
            float2 f1 = __half22float2(a21[x]);
            fa0[2 * x]     += f0.x;
            fa0[2 * x + 1] += f0.y;
            fa1[2 * x]     += f1.x;
            fa1[2 * x + 1] += f1.y;
        }
    }

    *(float4*)(pb0 + t * 8)     = make_float4(fa0[0], fa0[1], fa0[2], fa0[3]);
    *(float4*)(pb0 + t * 8 + 4) = make_float4(fa0[4], fa0[5], fa0[6], fa0[7]);
    *(float4*)(pb1 + t * 8)     = make_float4(fa1[0], fa1[1], fa1[2], fa1[3]);
    *(float4*)(pb1 + t * 8 + 4) = make_float4(fa1[4], fa1[5], fa1[6], fa1[7]);
    if (t == 0) { pb0[32] = l0; pb1[32] = l1; }
}

// One launch. 72 blocks per chunk. Part units: K3 0..3, K5 4..9, K7 10..16.
// Block ranges (K7 heaviest first): K7 [0,504), K5 [504,936), K3 [936,1224).
__global__ __launch_bounds__(256, 4) void na_partial_all_kernel(
    const __half* __restrict__ gqh,
    const __half* __restrict__ kh, const __half* __restrict__ vh,
    float* __restrict__ part)
{
    const int b = blockIdx.x;
    if (b < 504) {
        const int c = b / 72;
        na_body<7>(gqh, kh, vh, part + (size_t)(10 + c) * PART_UNIT, 4, b - c * 72, c);
    } else if (b < 936) {
        const int bb = b - 504;
        const int c = bb / 72;
        na_body<5>(gqh, kh, vh, part + (size_t)(4 + c) * PART_UNIT, 2, bb - c * 72, c);
    } else {
        const int bb = b - 936;
        const int c = bb / 72;
        na_body<3>(gqh, kh, vh, part + (size_t)c * PART_UNIT, 0, bb - c * 72, c);
    }
}

// ---------------------------------------------------------------------------
// Combine partials (plain sums; zero records harmless) -> g_y.
// scale s: cnt = {4,6,7}[s], unit base = {0,4,10}[s]. 110592 threads.
// ---------------------------------------------------------------------------
__global__ __launch_bounds__(256) void na_combine_kernel(
    const float* __restrict__ part, float* __restrict__ y)
{
    const int g = blockIdx.x * 256 + threadIdx.x;
    const int t = g & 3;
    int r = g >> 2;
    const int w = r % 24; r /= 24;
    const int h = r % 24; r /= 24;
    const int d = r & 7;  r >>= 3;
    const int head = r & 1;
    const int s = r >> 1;

    const int cnt   = (s == 0) ? 4 : (s == 1) ? 6 : 7;
    const int ubase = (s == 0) ? 0 : (s == 1) ? 4 : 10;
    const size_t base = (size_t)PART_UNIT * (size_t)ubase;
    const int qidx = ((head * Dd + d) * Hh + h) * Ww + w;

    float L = 0.f;
    float o[8];
#pragma unroll
    for (int i = 0; i < 8; i++) o[i] = 0.f;
    for (int c = 0; c < cnt; c++) {
        const float* pb = part + base + (size_t)c * PART_UNIT
                        + (size_t)qidx * PART_STRIDE;
        L += pb[32];
        float4 a0 = *(const float4*)(pb + t * 8);
        float4 a1 = *(const float4*)(pb + t * 8 + 4);
        o[0] += a0.x; o[1] += a0.y; o[2] += a0.z; o[3] += a0.w;
        o[4] += a1.x; o[5] += a1.y; o[6] += a1.z; o[7] += a1.w;
    }
    float inv = 1.f / L;
    const int vr = (d * Hh + h) * Ww + w;
    float* yp = y + (size_t)vr * DIMC + s * 64 + head * 32 + t * 8;
    *(float4*)yp       = make_float4(o[0] * inv, o[1] * inv, o[2] * inv, o[3] * inv);
    *(float4*)(yp + 4) = make_float4(o[4] * inv, o[5] * inv, o[6] * inv, o[7] * inv);
}

// ---------------------------------------------------------------------------
// Launch
// ---------------------------------------------------------------------------
extern "C" void kernel_launch(void* const* d_in, const int* in_sizes, int n_in,
                              void* d_out, int out_size)
{
    (void)in_sizes; (void)n_in; (void)out_size;
    const float* x      = (const float*)d_in[0];
    const float* W_qkv  = (const float*)d_in[1];
    const float* b_qkv  = (const float*)d_in[2];
    const float* W_proj = (const float*)d_in[3];
    const float* b_proj = (const float*)d_in[4];
    float* out = (float*)d_out;

    __half* qh;   cudaGetSymbolAddress((void**)&qh,   g_qh);
    __half* kh;   cudaGetSymbolAddress((void**)&kh,   g_kh);
    __half* vh;   cudaGetSymbolAddress((void**)&vh,   g_vh);
    float*  y;    cudaGetSymbolAddress((void**)&y,    g_y);
    float*  part; cudaGetSymbolAddress((void**)&part, g_part);
    float*  psum; cudaGetSymbolAddress((void**)&psum, g_psum);

    // 1) fused QKV GEMM + fp16 pack (324 blocks, double-buffered)
    gemm_qkv_kernel<<<dim3(576 / 64, NV / 128), 256>>>(
        x, W_qkv, b_qkv, qh, kh, vh, NV, 576, DIMC);

    // 2) all-scale NA3D partials, d-paired, 1 union slice/chunk (1224 blocks)
    na_partial_all_kernel<<<1224, 256>>>(qh, kh, vh, part);

    // 3) combine partials -> y
    na_combine_kernel<<<110592 / 256, 256>>>(part, y);

    // 4) proj GEMM, split-K=4 in ONE launch (3 x 36 x 4 = 432 blocks, BM=128)
    gemm_splitk_kernel<<<dim3(DIMC / 64, NV / 128, 4), 256>>>(
        y, W_proj, psum, NV, DIMC, DIMC, 3);

    // 5) out = sum(psum[0..3]) + bias
    splitk_reduce4_kernel<<<(NV * DIMC / 4) / 256, 256>>>(psum, b_proj, out);
}